// round 15
// baseline (speedup 1.0000x reference)
#include <cuda_runtime.h>
#include <cuda_fp16.h>
#include <cstdint>

// ---------------------------------------------------------------------------
// Transformer block: B=2, T=2048, C=1024, H=16 (hd=64), fp32 in/out.
// All GEMMs + attention on mma.sync m16n8k16 fp16 (fp32 accumulate).
// fp16 has the same 10 mantissa bits as tf32; every producer converts with RN.
// tcgen05 unavailable: harness PTX target is compute_103 (no 'a').
// ---------------------------------------------------------------------------

constexpr int Cdim = 1024;
constexpr int NH   = 16;
constexpr int HD   = 64;
constexpr int Tdim = 2048;
constexpr int Bdim = 2;
constexpr int MR   = Bdim * Tdim;   // 4096 rows
constexpr int FF   = 4 * Cdim;      // 4096

// Scratch (static device arrays — no runtime allocation).
__device__ __align__(16) __half g_h  [MR * Cdim];
__device__ __align__(16) __half g_qb [MR * Cdim];
__device__ __align__(16) __half g_kb [MR * Cdim];
__device__ __align__(16) __half g_vb [MR * Cdim];
__device__ __align__(16) __half g_y  [MR * Cdim];
__device__ __align__(16) float  g_x2 [MR * Cdim];
__device__ __align__(16) __half g_h2 [MR * Cdim];
__device__ __align__(16) __half g_mb [MR * FF];
// Transposed fp16 weights [N,K].
__device__ __align__(16) __half g_wqt[Cdim * Cdim];
__device__ __align__(16) __half g_wkt[Cdim * Cdim];
__device__ __align__(16) __half g_wvt[Cdim * Cdim];
__device__ __align__(16) __half g_wpt[Cdim * Cdim];
__device__ __align__(16) __half g_w1t[Cdim * FF];
__device__ __align__(16) __half g_w2t[Cdim * FF];

__device__ __forceinline__ void mma_f16(float* d, const uint32_t* a,
                                        uint32_t b0, uint32_t b1) {
    asm volatile(
        "mma.sync.aligned.m16n8k16.row.col.f32.f16.f16.f32 "
        "{%0,%1,%2,%3},{%4,%5,%6,%7},{%8,%9},{%0,%1,%2,%3};\n"
        : "+f"(d[0]), "+f"(d[1]), "+f"(d[2]), "+f"(d[3])
        : "r"(a[0]), "r"(a[1]), "r"(a[2]), "r"(a[3]), "r"(b0), "r"(b1));
}

__device__ __forceinline__ uint32_t pack_h2(float a, float b) {
    const __half2 h = __floats2half2_rn(a, b);
    return *reinterpret_cast<const uint32_t*>(&h);
}

__device__ __forceinline__ void cp16(uint32_t dst, const void* src) {
    asm volatile("cp.async.cg.shared.global [%0], [%1], 16;\n"
                 :: "r"(dst), "l"(src));
}

// ---------------------------------------------------------------------------
// Weight transpose + fp16 convert: T[n,k] = half(W[k,n]).
// ---------------------------------------------------------------------------
__global__ void transpose_kernel(const float* __restrict__ Wa,
                                 const float* __restrict__ Wb,
                                 const float* __restrict__ Wc,
                                 __half* __restrict__ Ta, __half* __restrict__ Tb,
                                 __half* __restrict__ Tc, int K, int N) {
    const int z = blockIdx.z;
    const float* W = (z == 0) ? Wa : (z == 1) ? Wb : Wc;
    __half* T      = (z == 0) ? Ta : (z == 1) ? Tb : Tc;
    __shared__ float tile[32][33];
    const int n0 = blockIdx.x * 32, k0 = blockIdx.y * 32;
    const int tx = threadIdx.x, ty = threadIdx.y;     // 32 x 8
    #pragma unroll
    for (int r = ty; r < 32; r += 8)
        tile[r][tx] = W[(size_t)(k0 + r) * N + n0 + tx];
    __syncthreads();
    #pragma unroll
    for (int r = ty; r < 32; r += 8)
        T[(size_t)(n0 + r) * K + k0 + tx] = __float2half_rn(tile[tx][r]);
}

// ---------------------------------------------------------------------------
// LayerNorm: one block per row (C=1024); fp16 output (feeds GEMM A).
// ---------------------------------------------------------------------------
__global__ void ln_kernel(const float4* __restrict__ x,
                          const float4* __restrict__ g,
                          const float4* __restrict__ b,
                          __half2* __restrict__ out) {
    const int row = blockIdx.x;
    const int t   = threadIdx.x;
    const float4 v = x[(size_t)row * 256 + t];
    float s = v.x + v.y + v.z + v.w;
    float q = v.x * v.x + v.y * v.y + v.z * v.z + v.w * v.w;
    #pragma unroll
    for (int o = 16; o > 0; o >>= 1) {
        s += __shfl_down_sync(0xffffffffu, s, o);
        q += __shfl_down_sync(0xffffffffu, q, o);
    }
    __shared__ float rs[8], rq[8];
    __shared__ float s_mean, s_rstd;
    const int wid = t >> 5, lane = t & 31;
    if (lane == 0) { rs[wid] = s; rq[wid] = q; }
    __syncthreads();
    if (t == 0) {
        float S = 0.f, Q = 0.f;
        #pragma unroll
        for (int i = 0; i < 8; i++) { S += rs[i]; Q += rq[i]; }
        const float mean = S * (1.0f / Cdim);
        const float var  = Q * (1.0f / Cdim) - mean * mean;
        s_mean = mean;
        s_rstd = rsqrtf(var + 1e-5f);
    }
    __syncthreads();
    const float mean = s_mean, rstd = s_rstd;
    const float4 G = g[t], Bv = b[t];
    out[(size_t)row * 512 + t * 2] =
        __floats2half2_rn((v.x - mean) * rstd * G.x + Bv.x,
                          (v.y - mean) * rstd * G.y + Bv.y);
    out[(size_t)row * 512 + t * 2 + 1] =
        __floats2half2_rn((v.z - mean) * rstd * G.z + Bv.z,
                          (v.w - mean) * rstd * G.w + Bv.w);
}

// ---------------------------------------------------------------------------
// fp16 tensor-core GEMM, cp.async 4-stage pipeline.
// C[M,N] = A[M,K] @ Bt[N,K]^T + bias (+ epilogue).
// 128x128x32 CTA tile, 8 warps (64x32 warp tile), m16n8k16 fp16 mma.
// Smem rows: 64B data + pad to 80B -> conflict-free fragment LDS
// (bank = (20*g + tk) % 32 is a permutation).
// blockIdx.z selects (Bt, bias, out) — QKV fusion.
// EPI: 0 bias, 1 bias+exact GELU, 2 bias+residual. HOUT: fp16 output.
// ---------------------------------------------------------------------------
constexpr int EPI_BIAS = 0;
constexpr int EPI_GELU = 1;
constexpr int EPI_RES  = 2;

constexpr int HG_BK     = 32;
constexpr int HG_STAGES = 4;
constexpr int HG_PADB   = 80;                         // bytes per smem row
constexpr int HG_TILE_B = 128 * HG_PADB;              // 10240 B per operand
constexpr int HG_STAGE_B = 2 * HG_TILE_B;             // 20480 B per stage
constexpr int HG_SMEM   = HG_STAGES * HG_STAGE_B;     // 81920 B

template <int EPI, bool HOUT>
__global__ __launch_bounds__(256, 2)
void hgemm_kernel(const __half* __restrict__ A,
                  const __half* __restrict__ Bt0, const __half* __restrict__ Bt1,
                  const __half* __restrict__ Bt2,
                  const float* __restrict__ bias0, const float* __restrict__ bias1,
                  const float* __restrict__ bias2,
                  const float* __restrict__ res,
                  void* __restrict__ C0, void* __restrict__ C1,
                  void* __restrict__ C2,
                  int M, int N, int K) {
    const int z = blockIdx.z;
    const __half* Bt  = (z == 0) ? Bt0   : (z == 1) ? Bt1   : Bt2;
    const float* bias = (z == 0) ? bias0 : (z == 1) ? bias1 : bias2;
    void*        Cout = (z == 0) ? C0    : (z == 1) ? C1    : C2;

    extern __shared__ char smem[];
    const uint32_t sbase = (uint32_t)__cvta_generic_to_shared(smem);

    const int tid  = threadIdx.x;
    const int lane = tid & 31;
    const int warp = tid >> 5;
    const int wRow = (warp & 1) * 64;
    const int wCol = (warp >> 1) * 32;
    const int g    = lane >> 2;            // 0..7
    const int tk   = lane & 3;             // 0..3

    const int cRow = blockIdx.y * 128;
    const int cCol = blockIdx.x * 128;
    const __half* Ag = A  + (size_t)cRow * K;
    const __half* Bg = Bt + (size_t)cCol * K;

    // 512 16B-chunks per operand per stage (128 rows x 4), 2 A + 2 B per thread.
    const int r0 = tid >> 2, c0 = tid & 3;
    const int r1 = r0 + 64;

    auto issue = [&](int k0, int stg) {
        const uint32_t aB = sbase + (uint32_t)stg * HG_STAGE_B;
        const uint32_t bB = aB + HG_TILE_B;
        cp16(aB + (uint32_t)(r0 * HG_PADB + c0 * 16), Ag + (size_t)r0 * K + k0 + c0 * 8);
        cp16(aB + (uint32_t)(r1 * HG_PADB + c0 * 16), Ag + (size_t)r1 * K + k0 + c0 * 8);
        cp16(bB + (uint32_t)(r0 * HG_PADB + c0 * 16), Bg + (size_t)r0 * K + k0 + c0 * 8);
        cp16(bB + (uint32_t)(r1 * HG_PADB + c0 * 16), Bg + (size_t)r1 * K + k0 + c0 * 8);
    };

    const int nIter = K / HG_BK;

    issue(0, 0);
    asm volatile("cp.async.commit_group;\n");
    issue(HG_BK, 1);
    asm volatile("cp.async.commit_group;\n");
    issue(2 * HG_BK, 2);
    asm volatile("cp.async.commit_group;\n");

    float acc[4][4][4] = {};

    for (int it = 0; it < nIter; it++) {
        asm volatile("cp.async.wait_group 2;\n");
        __syncthreads();

        if (it + 3 < nIter) issue((it + 3) * HG_BK, (it + 3) % HG_STAGES);
        asm volatile("cp.async.commit_group;\n");

        const uint32_t* As = reinterpret_cast<const uint32_t*>(
            smem + (it % HG_STAGES) * HG_STAGE_B);
        const uint32_t* Bs = As + HG_TILE_B / 4;

        #pragma unroll
        for (int kc = 0; kc < 2; kc++) {              // two k16 chunks
            uint32_t afr[4][4], bfr[4][2];
            #pragma unroll
            for (int i = 0; i < 4; i++) {
                const int m = wRow + i * 16 + g;
                const int idx = m * 20 + kc * 8 + tk;
                afr[i][0] = As[idx];
                afr[i][1] = As[idx + 160];            // row m+8
                afr[i][2] = As[idx + 4];              // +16B (k+8 pair)
                afr[i][3] = As[idx + 164];
            }
            #pragma unroll
            for (int j = 0; j < 4; j++) {
                const int n = wCol + j * 8 + g;
                const int idx = n * 20 + kc * 8 + tk;
                bfr[j][0] = Bs[idx];
                bfr[j][1] = Bs[idx + 4];
            }
            #pragma unroll
            for (int i = 0; i < 4; i++)
                #pragma unroll
                for (int j = 0; j < 4; j++)
                    mma_f16(acc[i][j], afr[i], bfr[j][0], bfr[j][1]);
        }
    }

    // Epilogue: c0,c1 at (row g, cols 2tk,2tk+1); c2,c3 at row g+8.
    #pragma unroll
    for (int i = 0; i < 4; i++) {
        const size_t rr0 = (size_t)cRow + wRow + i * 16 + g;
        const size_t rr1 = rr0 + 8;
        #pragma unroll
        for (int j = 0; j < 4; j++) {
            const int c = cCol + wCol + j * 8 + 2 * tk;
            const float b0 = bias[c], b1 = bias[c + 1];
            float v00 = acc[i][j][0] + b0, v01 = acc[i][j][1] + b1;
            float v10 = acc[i][j][2] + b0, v11 = acc[i][j][3] + b1;
            if (EPI == EPI_GELU) {
                v00 = 0.5f * v00 * (1.0f + erff(v00 * 0.70710678118654752f));
                v01 = 0.5f * v01 * (1.0f + erff(v01 * 0.70710678118654752f));
                v10 = 0.5f * v10 * (1.0f + erff(v10 * 0.70710678118654752f));
                v11 = 0.5f * v11 * (1.0f + erff(v11 * 0.70710678118654752f));
            }
            if (EPI == EPI_RES) {
                const float2 q0 = *reinterpret_cast<const float2*>(&res[rr0 * N + c]);
                const float2 q1 = *reinterpret_cast<const float2*>(&res[rr1 * N + c]);
                v00 += q0.x; v01 += q0.y;
                v10 += q1.x; v11 += q1.y;
            }
            if (HOUT) {
                __half* Ch = reinterpret_cast<__half*>(Cout);
                *reinterpret_cast<__half2*>(&Ch[rr0 * N + c]) = __floats2half2_rn(v00, v01);
                *reinterpret_cast<__half2*>(&Ch[rr1 * N + c]) = __floats2half2_rn(v10, v11);
            } else {
                float* Cf = reinterpret_cast<float*>(Cout);
                *reinterpret_cast<float2*>(&Cf[rr0 * N + c]) = make_float2(v00, v01);
                *reinterpret_cast<float2*>(&Cf[rr1 * N + c]) = make_float2(v10, v11);
            }
        }
    }
}

// ---------------------------------------------------------------------------
// Fused causal attention on mma.sync fp16, hd=64.
// CTA: 128 q rows (8 warps x 16 q), key tiles of 64.
// Ks[key][hd] fp16 (144B pad rows); Vst[hd][key] fp16 (transposed at load).
// Max-free softmax; S C-fragment pairs (cols 2tk,2tk+1) feed the fp16
// A-fragment of P.V directly — no shuffle permutation needed.
// ---------------------------------------------------------------------------
constexpr int KPB = 144;   // bytes per smem row: 128 data + 16 pad

__global__ __launch_bounds__(256, 2)
void attn_h_kernel(const __half* __restrict__ Q, const __half* __restrict__ K,
                   const __half* __restrict__ V, __half* __restrict__ Y) {
    __shared__ __align__(16) unsigned char KsRaw[64 * KPB];
    __shared__ __align__(16) unsigned char VtRaw[64 * KPB];
    const uint32_t* KsW = reinterpret_cast<const uint32_t*>(KsRaw);
    const uint32_t* VtW = reinterpret_cast<const uint32_t*>(VtRaw);

    const int tid  = threadIdx.x;
    const int lane = tid & 31;
    const int warp = tid >> 5;
    const int g  = lane >> 2;
    const int tk = lane & 3;
    const int qTile = blockIdx.x;
    const int bh = blockIdx.y;
    const int b = bh >> 4, h = bh & 15;
    const size_t base = (size_t)b * Tdim * Cdim + (size_t)h * HD;
    const int q0 = qTile * 128 + warp * 16;

    // Q fragments: 4 k16 chunks x 4 regs (fp16x2 pairs straight from gmem).
    uint32_t qf[4][4];
    #pragma unroll
    for (int c = 0; c < 4; c++) {
        const __half* q_r0 = Q + base + (size_t)(q0 + g)     * Cdim + c * 16;
        const __half* q_r1 = Q + base + (size_t)(q0 + g + 8) * Cdim + c * 16;
        qf[c][0] = *reinterpret_cast<const uint32_t*>(q_r0 + 2 * tk);
        qf[c][1] = *reinterpret_cast<const uint32_t*>(q_r1 + 2 * tk);
        qf[c][2] = *reinterpret_cast<const uint32_t*>(q_r0 + 2 * tk + 8);
        qf[c][3] = *reinterpret_cast<const uint32_t*>(q_r1 + 2 * tk + 8);
    }

    float oacc[8][4] = {};
    float lsum0 = 0.f, lsum1 = 0.f;

    const int nTiles = qTile * 2 + 2;
    for (int kt = 0; kt < nTiles; kt++) {
        const int kbase = kt * 64;
        // Load K (direct) and V (transposed) tiles: 64 rows x 8 uint4.
        #pragma unroll
        for (int r = 0; r < 2; r++) {
            const int lin = tid + r * 256;               // 0..511
            const int j = lin >> 3, c8 = lin & 7;
            const __half* gp = K + base + (size_t)(kbase + j) * Cdim + c8 * 8;
            *reinterpret_cast<uint4*>(KsRaw + j * KPB + c8 * 16) =
                *reinterpret_cast<const uint4*>(gp);
            const __half* vp = V + base + (size_t)(kbase + j) * Cdim + c8 * 8;
            const uint4 vv = *reinterpret_cast<const uint4*>(vp);
            const __half* vh = reinterpret_cast<const __half*>(&vv);
            #pragma unroll
            for (int u = 0; u < 8; u++)
                *reinterpret_cast<__half*>(VtRaw + (c8 * 8 + u) * KPB + j * 2) = vh[u];
        }
        __syncthreads();

        if (kbase <= q0 + 15) {
            const bool full = (kbase + 63 <= q0);
            #pragma unroll
            for (int kc = 0; kc < 4; kc++) {             // 16-key chunks
                float s0a[4] = {0.f, 0.f, 0.f, 0.f};     // keys kc*16+0..7
                float s1a[4] = {0.f, 0.f, 0.f, 0.f};     // keys kc*16+8..15
                const int kr0 = (kc * 16 + g) * 36;
                const int kr1 = (kc * 16 + 8 + g) * 36;
                #pragma unroll
                for (int cd = 0; cd < 4; cd++) {         // hd k16 chunks
                    const int o = cd * 8 + tk;
                    mma_f16(s0a, qf[cd], KsW[kr0 + o], KsW[kr0 + o + 4]);
                    mma_f16(s1a, qf[cd], KsW[kr1 + o], KsW[kr1 + o + 4]);
                }
                float p00 = __expf(s0a[0] * 0.125f);
                float p01 = __expf(s0a[1] * 0.125f);
                float p02 = __expf(s0a[2] * 0.125f);
                float p03 = __expf(s0a[3] * 0.125f);
                float p10 = __expf(s1a[0] * 0.125f);
                float p11 = __expf(s1a[1] * 0.125f);
                float p12 = __expf(s1a[2] * 0.125f);
                float p13 = __expf(s1a[3] * 0.125f);
                if (!full) {
                    const int k0a = kbase + kc * 16 + 2 * tk;
                    const int k0b = k0a + 8;
                    const int rq0 = q0 + g, rq1 = q0 + g + 8;
                    if (k0a     > rq0) p00 = 0.f;
                    if (k0a + 1 > rq0) p01 = 0.f;
                    if (k0a     > rq1) p02 = 0.f;
                    if (k0a + 1 > rq1) p03 = 0.f;
                    if (k0b     > rq0) p10 = 0.f;
                    if (k0b + 1 > rq0) p11 = 0.f;
                    if (k0b     > rq1) p12 = 0.f;
                    if (k0b + 1 > rq1) p13 = 0.f;
                }
                lsum0 += p00 + p01 + p10 + p11;
                lsum1 += p02 + p03 + p12 + p13;
                uint32_t afr[4];
                afr[0] = pack_h2(p00, p01);   // row g,   keys 2tk,2tk+1
                afr[1] = pack_h2(p02, p03);   // row g+8, keys 2tk,2tk+1
                afr[2] = pack_h2(p10, p11);   // row g,   keys 8+2tk,+1
                afr[3] = pack_h2(p12, p13);   // row g+8
                #pragma unroll
                for (int nb = 0; nb < 8; nb++) {
                    const int o = (nb * 8 + g) * 36 + kc * 8 + tk;
                    mma_f16(oacc[nb], afr, VtW[o], VtW[o + 4]);
                }
            }
        }
        __syncthreads();
    }

    lsum0 += __shfl_xor_sync(0xffffffffu, lsum0, 1);
    lsum0 += __shfl_xor_sync(0xffffffffu, lsum0, 2);
    lsum1 += __shfl_xor_sync(0xffffffffu, lsum1, 1);
    lsum1 += __shfl_xor_sync(0xffffffffu, lsum1, 2);
    const float inv0 = 1.0f / lsum0;
    const float inv1 = 1.0f / lsum1;

    #pragma unroll
    for (int nb = 0; nb < 8; nb++) {
        const int c = nb * 8 + 2 * tk;
        *reinterpret_cast<__half2*>(&Y[base + (size_t)(q0 + g) * Cdim + c]) =
            __floats2half2_rn(oacc[nb][0] * inv0, oacc[nb][1] * inv0);
        *reinterpret_cast<__half2*>(&Y[base + (size_t)(q0 + g + 8) * Cdim + c]) =
            __floats2half2_rn(oacc[nb][2] * inv1, oacc[nb][3] * inv1);
    }
}

// ---------------------------------------------------------------------------
// Launch sequence (graph-capturable).
// ---------------------------------------------------------------------------
extern "C" void kernel_launch(void* const* d_in, const int* in_sizes, int n_in,
                              void* d_out, int out_size) {
    (void)in_sizes; (void)n_in; (void)out_size;
    const float* x    = (const float*)d_in[0];
    const float* ln1g = (const float*)d_in[1];
    const float* ln1b = (const float*)d_in[2];
    const float* Wq   = (const float*)d_in[3];
    const float* bq   = (const float*)d_in[4];
    const float* Wk   = (const float*)d_in[5];
    const float* bk   = (const float*)d_in[6];
    const float* Wv   = (const float*)d_in[7];
    const float* bv   = (const float*)d_in[8];
    const float* Wp   = (const float*)d_in[9];
    const float* bp   = (const float*)d_in[10];
    const float* ln2g = (const float*)d_in[11];
    const float* ln2b = (const float*)d_in[12];
    const float* W1   = (const float*)d_in[13];
    const float* b1   = (const float*)d_in[14];
    const float* W2   = (const float*)d_in[15];
    const float* b2   = (const float*)d_in[16];
    float* out = (float*)d_out;

    __half *h, *qb, *kb, *vb, *y, *h2, *mb;
    __half *wqt, *wkt, *wvt, *wpt, *w1t, *w2t;
    float *x2;
    cudaGetSymbolAddress((void**)&h,  g_h);
    cudaGetSymbolAddress((void**)&qb, g_qb);
    cudaGetSymbolAddress((void**)&kb, g_kb);
    cudaGetSymbolAddress((void**)&vb, g_vb);
    cudaGetSymbolAddress((void**)&y,  g_y);
    cudaGetSymbolAddress((void**)&x2, g_x2);
    cudaGetSymbolAddress((void**)&h2, g_h2);
    cudaGetSymbolAddress((void**)&mb, g_mb);
    cudaGetSymbolAddress((void**)&wqt, g_wqt);
    cudaGetSymbolAddress((void**)&wkt, g_wkt);
    cudaGetSymbolAddress((void**)&wvt, g_wvt);
    cudaGetSymbolAddress((void**)&wpt, g_wpt);
    cudaGetSymbolAddress((void**)&w1t, g_w1t);
    cudaGetSymbolAddress((void**)&w2t, g_w2t);

    static bool attr_done = false;
    if (!attr_done) {
        cudaFuncSetAttribute((const void*)hgemm_kernel<EPI_BIAS, true>,
            cudaFuncAttributeMaxDynamicSharedMemorySize, HG_SMEM);
        cudaFuncSetAttribute((const void*)hgemm_kernel<EPI_GELU, true>,
            cudaFuncAttributeMaxDynamicSharedMemorySize, HG_SMEM);
        cudaFuncSetAttribute((const void*)hgemm_kernel<EPI_RES, false>,
            cudaFuncAttributeMaxDynamicSharedMemorySize, HG_SMEM);
        attr_done = true;
    }

    const dim3 tblk(32, 8);
    transpose_kernel<<<dim3(32, 32, 3), tblk>>>(Wq, Wk, Wv, wqt, wkt, wvt,
                                                Cdim, Cdim);
    transpose_kernel<<<dim3(32, 32, 1), tblk>>>(Wp, Wp, Wp, wpt, wpt, wpt,
                                                Cdim, Cdim);
    transpose_kernel<<<dim3(128, 32, 1), tblk>>>(W1, W1, W1, w1t, w1t, w1t,
                                                 Cdim, FF);
    transpose_kernel<<<dim3(32, 128, 1), tblk>>>(W2, W2, W2, w2t, w2t, w2t,
                                                 FF, Cdim);

    const dim3 blk(256);
    const dim3 gQKV(Cdim / 128, MR / 128, 3);
    const dim3 gCC (Cdim / 128, MR / 128, 1);
    const dim3 gCF (FF   / 128, MR / 128, 1);
    const int  sm = HG_SMEM;

    ln_kernel<<<MR, 256>>>((const float4*)x, (const float4*)ln1g,
                           (const float4*)ln1b, (__half2*)h);
    hgemm_kernel<EPI_BIAS, true><<<gQKV, blk, sm>>>(
        h, wqt, wkt, wvt, bq, bk, bv, nullptr, qb, kb, vb, MR, Cdim, Cdim);
    attn_h_kernel<<<dim3(Tdim / 128, Bdim * NH), 256>>>(qb, kb, vb, y);
    hgemm_kernel<EPI_RES, false><<<gCC, blk, sm>>>(
        y, wpt, wpt, wpt, bp, bp, bp, x, x2, x2, x2, MR, Cdim, Cdim);
    ln_kernel<<<MR, 256>>>((const float4*)x2, (const float4*)ln2g,
                           (const float4*)ln2b, (__half2*)h2);
    hgemm_kernel<EPI_GELU, true><<<gCF, blk, sm>>>(
        h2, w1t, w1t, w1t, b1, b1, b1, nullptr, mb, mb, mb, MR, FF, Cdim);
    hgemm_kernel<EPI_RES, false><<<gCC, blk, sm>>>(
        mb, w2t, w2t, w2t, b2, b2, b2, x2, out, out, out, MR, Cdim, FF);
}

// round 16
// speedup vs baseline: 1.8940x; 1.8940x over previous
#include <cuda_runtime.h>
#include <cuda_fp16.h>
#include <cstdint>

// ---------------------------------------------------------------------------
// Transformer block: B=2, T=2048, C=1024, H=16 (hd=64), fp32 in/out.
// All GEMMs + attention on mma.sync m16n8k16 fp16 (fp32 accumulate),
// fragments loaded via ldmatrix (x4 / x4.trans).
// ---------------------------------------------------------------------------

constexpr int Cdim = 1024;
constexpr int NH   = 16;
constexpr int HD   = 64;
constexpr int Tdim = 2048;
constexpr int Bdim = 2;
constexpr int MR   = Bdim * Tdim;   // 4096 rows
constexpr int FF   = 4 * Cdim;      // 4096

// Scratch (static device arrays — no runtime allocation).
__device__ __align__(16) __half g_h  [MR * Cdim];
__device__ __align__(16) __half g_qb [MR * Cdim];
__device__ __align__(16) __half g_kb [MR * Cdim];
__device__ __align__(16) __half g_vb [MR * Cdim];
__device__ __align__(16) __half g_y  [MR * Cdim];
__device__ __align__(16) float  g_x2 [MR * Cdim];
__device__ __align__(16) __half g_h2 [MR * Cdim];
__device__ __align__(16) __half g_mb [MR * FF];
// Transposed fp16 weights [N,K].
__device__ __align__(16) __half g_wqt[Cdim * Cdim];
__device__ __align__(16) __half g_wkt[Cdim * Cdim];
__device__ __align__(16) __half g_wvt[Cdim * Cdim];
__device__ __align__(16) __half g_wpt[Cdim * Cdim];
__device__ __align__(16) __half g_w1t[Cdim * FF];
__device__ __align__(16) __half g_w2t[Cdim * FF];

__device__ __forceinline__ void mma_f16(float* d, const uint32_t* a,
                                        uint32_t b0, uint32_t b1) {
    asm volatile(
        "mma.sync.aligned.m16n8k16.row.col.f32.f16.f16.f32 "
        "{%0,%1,%2,%3},{%4,%5,%6,%7},{%8,%9},{%0,%1,%2,%3};\n"
        : "+f"(d[0]), "+f"(d[1]), "+f"(d[2]), "+f"(d[3])
        : "r"(a[0]), "r"(a[1]), "r"(a[2]), "r"(a[3]), "r"(b0), "r"(b1));
}

__device__ __forceinline__ void ldsm4(uint32_t* r, uint32_t addr) {
    asm volatile(
        "ldmatrix.sync.aligned.m8n8.x4.shared.b16 {%0,%1,%2,%3}, [%4];"
        : "=r"(r[0]), "=r"(r[1]), "=r"(r[2]), "=r"(r[3]) : "r"(addr));
}

__device__ __forceinline__ void ldsm4t(uint32_t* r, uint32_t addr) {
    asm volatile(
        "ldmatrix.sync.aligned.m8n8.x4.trans.shared.b16 {%0,%1,%2,%3}, [%4];"
        : "=r"(r[0]), "=r"(r[1]), "=r"(r[2]), "=r"(r[3]) : "r"(addr));
}

__device__ __forceinline__ uint32_t pack_h2(float a, float b) {
    const __half2 h = __floats2half2_rn(a, b);
    return *reinterpret_cast<const uint32_t*>(&h);
}

__device__ __forceinline__ void cp16(uint32_t dst, const void* src) {
    asm volatile("cp.async.cg.shared.global [%0], [%1], 16;\n"
                 :: "r"(dst), "l"(src));
}

// ---------------------------------------------------------------------------
// Weight transpose + fp16 convert: T[n,k] = half(W[k,n]).
// ---------------------------------------------------------------------------
__global__ void transpose_kernel(const float* __restrict__ Wa,
                                 const float* __restrict__ Wb,
                                 const float* __restrict__ Wc,
                                 __half* __restrict__ Ta, __half* __restrict__ Tb,
                                 __half* __restrict__ Tc, int K, int N) {
    const int z = blockIdx.z;
    const float* W = (z == 0) ? Wa : (z == 1) ? Wb : Wc;
    __half* T      = (z == 0) ? Ta : (z == 1) ? Tb : Tc;
    __shared__ float tile[32][33];
    const int n0 = blockIdx.x * 32, k0 = blockIdx.y * 32;
    const int tx = threadIdx.x, ty = threadIdx.y;     // 32 x 8
    #pragma unroll
    for (int r = ty; r < 32; r += 8)
        tile[r][tx] = W[(size_t)(k0 + r) * N + n0 + tx];
    __syncthreads();
    #pragma unroll
    for (int r = ty; r < 32; r += 8)
        T[(size_t)(n0 + r) * K + k0 + tx] = __float2half_rn(tile[tx][r]);
}

// ---------------------------------------------------------------------------
// LayerNorm: one block per row (C=1024); fp16 output (feeds GEMM A).
// ---------------------------------------------------------------------------
__global__ void ln_kernel(const float4* __restrict__ x,
                          const float4* __restrict__ g,
                          const float4* __restrict__ b,
                          __half2* __restrict__ out) {
    const int row = blockIdx.x;
    const int t   = threadIdx.x;
    const float4 v = x[(size_t)row * 256 + t];
    float s = v.x + v.y + v.z + v.w;
    float q = v.x * v.x + v.y * v.y + v.z * v.z + v.w * v.w;
    #pragma unroll
    for (int o = 16; o > 0; o >>= 1) {
        s += __shfl_down_sync(0xffffffffu, s, o);
        q += __shfl_down_sync(0xffffffffu, q, o);
    }
    __shared__ float rs[8], rq[8];
    __shared__ float s_mean, s_rstd;
    const int wid = t >> 5, lane = t & 31;
    if (lane == 0) { rs[wid] = s; rq[wid] = q; }
    __syncthreads();
    if (t == 0) {
        float S = 0.f, Q = 0.f;
        #pragma unroll
        for (int i = 0; i < 8; i++) { S += rs[i]; Q += rq[i]; }
        const float mean = S * (1.0f / Cdim);
        const float var  = Q * (1.0f / Cdim) - mean * mean;
        s_mean = mean;
        s_rstd = rsqrtf(var + 1e-5f);
    }
    __syncthreads();
    const float mean = s_mean, rstd = s_rstd;
    const float4 G = g[t], Bv = b[t];
    out[(size_t)row * 512 + t * 2] =
        __floats2half2_rn((v.x - mean) * rstd * G.x + Bv.x,
                          (v.y - mean) * rstd * G.y + Bv.y);
    out[(size_t)row * 512 + t * 2 + 1] =
        __floats2half2_rn((v.z - mean) * rstd * G.z + Bv.z,
                          (v.w - mean) * rstd * G.w + Bv.w);
}

// ---------------------------------------------------------------------------
// fp16 tensor-core GEMM, cp.async 4-stage pipeline, ldmatrix fragments.
// C[M,N] = A[M,K] @ Bt[N,K]^T + bias (+ epilogue).
// 128x128x32 CTA tile, 8 warps (64x32 warp tile), m16n8k16 fp16 mma.
// Smem rows 64B data + pad to 80B: ldmatrix row-sets are bank-conflict-free.
// blockIdx.z selects (Bt, bias, out) — QKV fusion.
// ---------------------------------------------------------------------------
constexpr int EPI_BIAS = 0;
constexpr int EPI_GELU = 1;
constexpr int EPI_RES  = 2;

constexpr int HG_BK     = 32;
constexpr int HG_STAGES = 4;
constexpr int HG_PADB   = 80;                         // bytes per smem row
constexpr int HG_TILE_B = 128 * HG_PADB;              // 10240 B per operand
constexpr int HG_STAGE_B = 2 * HG_TILE_B;             // 20480 B per stage
constexpr int HG_SMEM   = HG_STAGES * HG_STAGE_B;     // 81920 B

template <int EPI, bool HOUT>
__global__ __launch_bounds__(256, 2)
void hgemm_kernel(const __half* __restrict__ A,
                  const __half* __restrict__ Bt0, const __half* __restrict__ Bt1,
                  const __half* __restrict__ Bt2,
                  const float* __restrict__ bias0, const float* __restrict__ bias1,
                  const float* __restrict__ bias2,
                  const float* __restrict__ res,
                  void* __restrict__ C0, void* __restrict__ C1,
                  void* __restrict__ C2,
                  int M, int N, int K) {
    const int z = blockIdx.z;
    const __half* Bt  = (z == 0) ? Bt0   : (z == 1) ? Bt1   : Bt2;
    const float* bias = (z == 0) ? bias0 : (z == 1) ? bias1 : bias2;
    void*        Cout = (z == 0) ? C0    : (z == 1) ? C1    : C2;

    extern __shared__ char smem[];
    const uint32_t sbase = (uint32_t)__cvta_generic_to_shared(smem);

    const int tid  = threadIdx.x;
    const int lane = tid & 31;
    const int warp = tid >> 5;
    const int wRow = (warp & 1) * 64;
    const int wCol = (warp >> 1) * 32;
    const int g    = lane >> 2;
    const int tk   = lane & 3;

    // ldmatrix per-lane selectors.
    const int aSelRow = (lane & 7) + ((lane >> 3) & 1) * 8;   // m within tile
    const int aSelK   = (lane >> 4) * 8;                      // k half
    const int bSelN   = (lane & 7) + (lane >> 4) * 8;         // n within pair
    const int bSelK   = ((lane >> 3) & 1) * 8;                // k half

    const int cRow = blockIdx.y * 128;
    const int cCol = blockIdx.x * 128;
    const __half* Ag = A  + (size_t)cRow * K;
    const __half* Bg = Bt + (size_t)cCol * K;

    const int r0 = tid >> 2, c0 = tid & 3;
    const int r1 = r0 + 64;

    auto issue = [&](int k0, int stg) {
        const uint32_t aB = sbase + (uint32_t)stg * HG_STAGE_B;
        const uint32_t bB = aB + HG_TILE_B;
        cp16(aB + (uint32_t)(r0 * HG_PADB + c0 * 16), Ag + (size_t)r0 * K + k0 + c0 * 8);
        cp16(aB + (uint32_t)(r1 * HG_PADB + c0 * 16), Ag + (size_t)r1 * K + k0 + c0 * 8);
        cp16(bB + (uint32_t)(r0 * HG_PADB + c0 * 16), Bg + (size_t)r0 * K + k0 + c0 * 8);
        cp16(bB + (uint32_t)(r1 * HG_PADB + c0 * 16), Bg + (size_t)r1 * K + k0 + c0 * 8);
    };

    const int nIter = K / HG_BK;

    issue(0, 0);
    asm volatile("cp.async.commit_group;\n");
    issue(HG_BK, 1);
    asm volatile("cp.async.commit_group;\n");
    issue(2 * HG_BK, 2);
    asm volatile("cp.async.commit_group;\n");

    float acc[4][4][4] = {};

    for (int it = 0; it < nIter; it++) {
        asm volatile("cp.async.wait_group 2;\n");
        __syncthreads();

        if (it + 3 < nIter) issue((it + 3) * HG_BK, (it + 3) % HG_STAGES);
        asm volatile("cp.async.commit_group;\n");

        const uint32_t aB = sbase + (uint32_t)(it % HG_STAGES) * HG_STAGE_B;
        const uint32_t bB = aB + HG_TILE_B;

        #pragma unroll
        for (int kc = 0; kc < 2; kc++) {              // two k16 chunks
            uint32_t afr[4][4], bfr[2][4];
            #pragma unroll
            for (int i = 0; i < 4; i++)
                ldsm4(afr[i], aB + (uint32_t)((wRow + i * 16 + aSelRow) * HG_PADB
                                              + (kc * 16 + aSelK) * 2));
            #pragma unroll
            for (int jp = 0; jp < 2; jp++)
                ldsm4(bfr[jp], bB + (uint32_t)((wCol + jp * 16 + bSelN) * HG_PADB
                                               + (kc * 16 + bSelK) * 2));
            #pragma unroll
            for (int i = 0; i < 4; i++)
                #pragma unroll
                for (int j = 0; j < 4; j++)
                    mma_f16(acc[i][j], afr[i],
                            bfr[j >> 1][(j & 1) * 2], bfr[j >> 1][(j & 1) * 2 + 1]);
        }
    }

    // Epilogue: c0,c1 at (row g, cols 2tk,2tk+1); c2,c3 at row g+8.
    #pragma unroll
    for (int i = 0; i < 4; i++) {
        const size_t rr0 = (size_t)cRow + wRow + i * 16 + g;
        const size_t rr1 = rr0 + 8;
        #pragma unroll
        for (int j = 0; j < 4; j++) {
            const int c = cCol + wCol + j * 8 + 2 * tk;
            const float b0 = bias[c], b1 = bias[c + 1];
            float v00 = acc[i][j][0] + b0, v01 = acc[i][j][1] + b1;
            float v10 = acc[i][j][2] + b0, v11 = acc[i][j][3] + b1;
            if (EPI == EPI_GELU) {
                v00 = 0.5f * v00 * (1.0f + erff(v00 * 0.70710678118654752f));
                v01 = 0.5f * v01 * (1.0f + erff(v01 * 0.70710678118654752f));
                v10 = 0.5f * v10 * (1.0f + erff(v10 * 0.70710678118654752f));
                v11 = 0.5f * v11 * (1.0f + erff(v11 * 0.70710678118654752f));
            }
            if (EPI == EPI_RES) {
                const float2 q0 = *reinterpret_cast<const float2*>(&res[rr0 * N + c]);
                const float2 q1 = *reinterpret_cast<const float2*>(&res[rr1 * N + c]);
                v00 += q0.x; v01 += q0.y;
                v10 += q1.x; v11 += q1.y;
            }
            if (HOUT) {
                __half* Ch = reinterpret_cast<__half*>(Cout);
                *reinterpret_cast<__half2*>(&Ch[rr0 * N + c]) = __floats2half2_rn(v00, v01);
                *reinterpret_cast<__half2*>(&Ch[rr1 * N + c]) = __floats2half2_rn(v10, v11);
            } else {
                float* Cf = reinterpret_cast<float*>(Cout);
                *reinterpret_cast<float2*>(&Cf[rr0 * N + c]) = make_float2(v00, v01);
                *reinterpret_cast<float2*>(&Cf[rr1 * N + c]) = make_float2(v10, v11);
            }
        }
    }
}

// ---------------------------------------------------------------------------
// Fused causal attention on mma.sync fp16, hd=64, ldmatrix fragments.
// CTA: 128 q rows (8 warps x 16 q), key tiles of 64 in smem (144B rows).
// K fragments: ldmatrix.x4 (one per hd k16-chunk, covers both key n-tiles).
// V fragments: ldmatrix.x4.trans straight off row-major V smem.
// Max-free softmax; S C-fragment pairs feed the fp16 A-fragment of P.V.
// ---------------------------------------------------------------------------
constexpr int KPB = 144;   // bytes per smem row: 128 data + 16 pad

__global__ __launch_bounds__(256, 2)
void attn_h_kernel(const __half* __restrict__ Q, const __half* __restrict__ K,
                   const __half* __restrict__ V, __half* __restrict__ Y) {
    __shared__ __align__(16) unsigned char KsRaw[64 * KPB];
    __shared__ __align__(16) unsigned char VsRaw[64 * KPB];
    const uint32_t Kbase = (uint32_t)__cvta_generic_to_shared(KsRaw);
    const uint32_t Vbase = (uint32_t)__cvta_generic_to_shared(VsRaw);

    const int tid  = threadIdx.x;
    const int lane = tid & 31;
    const int warp = tid >> 5;
    const int g  = lane >> 2;
    const int tk = lane & 3;
    const int qTile = blockIdx.x;
    const int bh = blockIdx.y;
    const int b = bh >> 4, h = bh & 15;
    const size_t base = (size_t)b * Tdim * Cdim + (size_t)h * HD;
    const int q0 = qTile * 128 + warp * 16;

    // ldmatrix selectors.
    const int kSelRow = (lane & 7) + (lane >> 4) * 8;        // key row (K, x4)
    const int kSelHd  = ((lane >> 3) & 1) * 8;               // hd half
    const int vSelKey = (lane & 7) + ((lane >> 3) & 1) * 8;  // key row (V, trans)
    const int vSelHd  = (lane >> 4) * 8;                     // hd half

    // Q fragments: 4 k16 chunks x 4 regs (fp16x2 pairs straight from gmem).
    uint32_t qf[4][4];
    #pragma unroll
    for (int c = 0; c < 4; c++) {
        const __half* q_r0 = Q + base + (size_t)(q0 + g)     * Cdim + c * 16;
        const __half* q_r1 = Q + base + (size_t)(q0 + g + 8) * Cdim + c * 16;
        qf[c][0] = *reinterpret_cast<const uint32_t*>(q_r0 + 2 * tk);
        qf[c][1] = *reinterpret_cast<const uint32_t*>(q_r1 + 2 * tk);
        qf[c][2] = *reinterpret_cast<const uint32_t*>(q_r0 + 2 * tk + 8);
        qf[c][3] = *reinterpret_cast<const uint32_t*>(q_r1 + 2 * tk + 8);
    }

    float oacc[8][4] = {};
    float lsum0 = 0.f, lsum1 = 0.f;

    const int nTiles = qTile * 2 + 2;
    for (int kt = 0; kt < nTiles; kt++) {
        const int kbase = kt * 64;
        // Load K and V tiles: 64 rows x 8 uint4 each (vectorized, no transpose).
        #pragma unroll
        for (int r = 0; r < 2; r++) {
            const int lin = tid + r * 256;               // 0..511
            const int j = lin >> 3, c8 = lin & 7;
            const size_t go = base + (size_t)(kbase + j) * Cdim + c8 * 8;
            *reinterpret_cast<uint4*>(KsRaw + j * KPB + c8 * 16) =
                *reinterpret_cast<const uint4*>(K + go);
            *reinterpret_cast<uint4*>(VsRaw + j * KPB + c8 * 16) =
                *reinterpret_cast<const uint4*>(V + go);
        }
        __syncthreads();

        if (kbase <= q0 + 15) {
            const bool full = (kbase + 63 <= q0);
            #pragma unroll
            for (int kc = 0; kc < 4; kc++) {             // 16-key chunks
                float s0a[4] = {0.f, 0.f, 0.f, 0.f};     // keys kc*16+0..7
                float s1a[4] = {0.f, 0.f, 0.f, 0.f};     // keys kc*16+8..15
                #pragma unroll
                for (int cd = 0; cd < 4; cd++) {         // hd k16 chunks
                    uint32_t kf[4];
                    ldsm4(kf, Kbase + (uint32_t)((kc * 16 + kSelRow) * KPB
                                                 + (cd * 16 + kSelHd) * 2));
                    mma_f16(s0a, qf[cd], kf[0], kf[1]);
                    mma_f16(s1a, qf[cd], kf[2], kf[3]);
                }
                float p00 = __expf(s0a[0] * 0.125f);
                float p01 = __expf(s0a[1] * 0.125f);
                float p02 = __expf(s0a[2] * 0.125f);
                float p03 = __expf(s0a[3] * 0.125f);
                float p10 = __expf(s1a[0] * 0.125f);
                float p11 = __expf(s1a[1] * 0.125f);
                float p12 = __expf(s1a[2] * 0.125f);
                float p13 = __expf(s1a[3] * 0.125f);
                if (!full) {
                    const int k0a = kbase + kc * 16 + 2 * tk;
                    const int k0b = k0a + 8;
                    const int rq0 = q0 + g, rq1 = q0 + g + 8;
                    if (k0a     > rq0) p00 = 0.f;
                    if (k0a + 1 > rq0) p01 = 0.f;
                    if (k0a     > rq1) p02 = 0.f;
                    if (k0a + 1 > rq1) p03 = 0.f;
                    if (k0b     > rq0) p10 = 0.f;
                    if (k0b + 1 > rq0) p11 = 0.f;
                    if (k0b     > rq1) p12 = 0.f;
                    if (k0b + 1 > rq1) p13 = 0.f;
                }
                lsum0 += p00 + p01 + p10 + p11;
                lsum1 += p02 + p03 + p12 + p13;
                uint32_t afr[4];
                afr[0] = pack_h2(p00, p01);   // row g,   keys 2tk,2tk+1
                afr[1] = pack_h2(p02, p03);   // row g+8, keys 2tk,2tk+1
                afr[2] = pack_h2(p10, p11);   // row g,   keys 8+2tk,+1
                afr[3] = pack_h2(p12, p13);   // row g+8
                #pragma unroll
                for (int nbp = 0; nbp < 4; nbp++) {      // hd n8 pairs
                    uint32_t vf[4];
                    ldsm4t(vf, Vbase + (uint32_t)((kc * 16 + vSelKey) * KPB
                                                  + (nbp * 16 + vSelHd) * 2));
                    mma_f16(oacc[2 * nbp],     afr, vf[0], vf[1]);
                    mma_f16(oacc[2 * nbp + 1], afr, vf[2], vf[3]);
                }
            }
        }
        __syncthreads();
    }

    lsum0 += __shfl_xor_sync(0xffffffffu, lsum0, 1);
    lsum0 += __shfl_xor_sync(0xffffffffu, lsum0, 2);
    lsum1 += __shfl_xor_sync(0xffffffffu, lsum1, 1);
    lsum1 += __shfl_xor_sync(0xffffffffu, lsum1, 2);
    const float inv0 = 1.0f / lsum0;
    const float inv1 = 1.0f / lsum1;

    #pragma unroll
    for (int nb = 0; nb < 8; nb++) {
        const int c = nb * 8 + 2 * tk;
        *reinterpret_cast<__half2*>(&Y[base + (size_t)(q0 + g) * Cdim + c]) =
            __floats2half2_rn(oacc[nb][0] * inv0, oacc[nb][1] * inv0);
        *reinterpret_cast<__half2*>(&Y[base + (size_t)(q0 + g + 8) * Cdim + c]) =
            __floats2half2_rn(oacc[nb][2] * inv1, oacc[nb][3] * inv1);
    }
}

// ---------------------------------------------------------------------------
// Launch sequence (graph-capturable).
// ---------------------------------------------------------------------------
extern "C" void kernel_launch(void* const* d_in, const int* in_sizes, int n_in,
                              void* d_out, int out_size) {
    (void)in_sizes; (void)n_in; (void)out_size;
    const float* x    = (const float*)d_in[0];
    const float* ln1g = (const float*)d_in[1];
    const float* ln1b = (const float*)d_in[2];
    const float* Wq   = (const float*)d_in[3];
    const float* bq   = (const float*)d_in[4];
    const float* Wk   = (const float*)d_in[5];
    const float* bk   = (const float*)d_in[6];
    const float* Wv   = (const float*)d_in[7];
    const float* bv   = (const float*)d_in[8];
    const float* Wp   = (const float*)d_in[9];
    const float* bp   = (const float*)d_in[10];
    const float* ln2g = (const float*)d_in[11];
    const float* ln2b = (const float*)d_in[12];
    const float* W1   = (const float*)d_in[13];
    const float* b1   = (const float*)d_in[14];
    const float* W2   = (const float*)d_in[15];
    const float* b2   = (const float*)d_in[16];
    float* out = (float*)d_out;

    __half *h, *qb, *kb, *vb, *y, *h2, *mb;
    __half *wqt, *wkt, *wvt, *wpt, *w1t, *w2t;
    float *x2;
    cudaGetSymbolAddress((void**)&h,  g_h);
    cudaGetSymbolAddress((void**)&qb, g_qb);
    cudaGetSymbolAddress((void**)&kb, g_kb);
    cudaGetSymbolAddress((void**)&vb, g_vb);
    cudaGetSymbolAddress((void**)&y,  g_y);
    cudaGetSymbolAddress((void**)&x2, g_x2);
    cudaGetSymbolAddress((void**)&h2, g_h2);
    cudaGetSymbolAddress((void**)&mb, g_mb);
    cudaGetSymbolAddress((void**)&wqt, g_wqt);
    cudaGetSymbolAddress((void**)&wkt, g_wkt);
    cudaGetSymbolAddress((void**)&wvt, g_wvt);
    cudaGetSymbolAddress((void**)&wpt, g_wpt);
    cudaGetSymbolAddress((void**)&w1t, g_w1t);
    cudaGetSymbolAddress((void**)&w2t, g_w2t);

    static bool attr_done = false;
    if (!attr_done) {
        cudaFuncSetAttribute((const void*)hgemm_kernel<EPI_BIAS, true>,
            cudaFuncAttributeMaxDynamicSharedMemorySize, HG_SMEM);
        cudaFuncSetAttribute((const void*)hgemm_kernel<EPI_GELU, true>,
            cudaFuncAttributeMaxDynamicSharedMemorySize, HG_SMEM);
        cudaFuncSetAttribute((const void*)hgemm_kernel<EPI_RES, false>,
            cudaFuncAttributeMaxDynamicSharedMemorySize, HG_SMEM);
        attr_done = true;
    }

    const dim3 tblk(32, 8);
    transpose_kernel<<<dim3(32, 32, 3), tblk>>>(Wq, Wk, Wv, wqt, wkt, wvt,
                                                Cdim, Cdim);
    transpose_kernel<<<dim3(32, 32, 1), tblk>>>(Wp, Wp, Wp, wpt, wpt, wpt,
                                                Cdim, Cdim);
    transpose_kernel<<<dim3(128, 32, 1), tblk>>>(W1, W1, W1, w1t, w1t, w1t,
                                                 Cdim, FF);
    transpose_kernel<<<dim3(32, 128, 1), tblk>>>(W2, W2, W2, w2t, w2t, w2t,
                                                 FF, Cdim);

    const dim3 blk(256);
    const dim3 gQKV(Cdim / 128, MR / 128, 3);
    const dim3 gCC (Cdim / 128, MR / 128, 1);
    const dim3 gCF (FF   / 128, MR / 128, 1);
    const int  sm = HG_SMEM;

    ln_kernel<<<MR, 256>>>((const float4*)x, (const float4*)ln1g,
                           (const float4*)ln1b, (__half2*)h);
    hgemm_kernel<EPI_BIAS, true><<<gQKV, blk, sm>>>(
        h, wqt, wkt, wvt, bq, bk, bv, nullptr, qb, kb, vb, MR, Cdim, Cdim);
    attn_h_kernel<<<dim3(Tdim / 128, Bdim * NH), 256>>>(qb, kb, vb, y);
    hgemm_kernel<EPI_RES, false><<<gCC, blk, sm>>>(
        y, wpt, wpt, wpt, bp, bp, bp, x, x2, x2, x2, MR, Cdim, Cdim);
    ln_kernel<<<MR, 256>>>((const float4*)x2, (const float4*)ln2g,
                           (const float4*)ln2b, (__half2*)h2);
    hgemm_kernel<EPI_GELU, true><<<gCF, blk, sm>>>(
        h2, w1t, w1t, w1t, b1, b1, b1, nullptr, mb, mb, mb, MR, FF, Cdim);
    hgemm_kernel<EPI_RES, false><<<gCC, blk, sm>>>(
        mb, w2t, w2t, w2t, b2, b2, b2, x2, out, out, out, MR, Cdim, FF);
}

// round 17
// speedup vs baseline: 2.0317x; 1.0727x over previous
#include <cuda_runtime.h>
#include <cuda_fp16.h>
#include <cstdint>

// ---------------------------------------------------------------------------
// Transformer block: B=2, T=2048, C=1024, H=16 (hd=64), fp32 in/out.
// All GEMMs + attention on mma.sync m16n8k16 fp16 (fp32 accumulate),
// fragments via ldmatrix. Weights consumed in native [K,N] layout via
// ldmatrix.x4.trans (no transpose pass; one fp32->fp16 convert kernel).
// ---------------------------------------------------------------------------

constexpr int Cdim = 1024;
constexpr int NH   = 16;
constexpr int HD   = 64;
constexpr int Tdim = 2048;
constexpr int Bdim = 2;
constexpr int MR   = Bdim * Tdim;   // 4096 rows
constexpr int FF   = 4 * Cdim;      // 4096

// Scratch (static device arrays — no runtime allocation).
__device__ __align__(16) __half g_h  [MR * Cdim];
__device__ __align__(16) __half g_qb [MR * Cdim];
__device__ __align__(16) __half g_kb [MR * Cdim];
__device__ __align__(16) __half g_vb [MR * Cdim];
__device__ __align__(16) __half g_y  [MR * Cdim];
__device__ __align__(16) float  g_x2 [MR * Cdim];
__device__ __align__(16) __half g_h2 [MR * Cdim];
__device__ __align__(16) __half g_mb [MR * FF];
// fp16 weights, native [K,N] layout.
__device__ __align__(16) __half g_wq [Cdim * Cdim];
__device__ __align__(16) __half g_wk [Cdim * Cdim];
__device__ __align__(16) __half g_wv [Cdim * Cdim];
__device__ __align__(16) __half g_wp [Cdim * Cdim];
__device__ __align__(16) __half g_w1 [Cdim * FF];
__device__ __align__(16) __half g_w2 [Cdim * FF];

__device__ __forceinline__ void mma_f16(float* d, const uint32_t* a,
                                        uint32_t b0, uint32_t b1) {
    asm volatile(
        "mma.sync.aligned.m16n8k16.row.col.f32.f16.f16.f32 "
        "{%0,%1,%2,%3},{%4,%5,%6,%7},{%8,%9},{%0,%1,%2,%3};\n"
        : "+f"(d[0]), "+f"(d[1]), "+f"(d[2]), "+f"(d[3])
        : "r"(a[0]), "r"(a[1]), "r"(a[2]), "r"(a[3]), "r"(b0), "r"(b1));
}

__device__ __forceinline__ void ldsm4(uint32_t* r, uint32_t addr) {
    asm volatile(
        "ldmatrix.sync.aligned.m8n8.x4.shared.b16 {%0,%1,%2,%3}, [%4];"
        : "=r"(r[0]), "=r"(r[1]), "=r"(r[2]), "=r"(r[3]) : "r"(addr));
}

__device__ __forceinline__ void ldsm4t(uint32_t* r, uint32_t addr) {
    asm volatile(
        "ldmatrix.sync.aligned.m8n8.x4.trans.shared.b16 {%0,%1,%2,%3}, [%4];"
        : "=r"(r[0]), "=r"(r[1]), "=r"(r[2]), "=r"(r[3]) : "r"(addr));
}

__device__ __forceinline__ uint32_t pack_h2(float a, float b) {
    const __half2 h = __floats2half2_rn(a, b);
    return *reinterpret_cast<const uint32_t*>(&h);
}

__device__ __forceinline__ void cp16(uint32_t dst, const void* src) {
    asm volatile("cp.async.cg.shared.global [%0], [%1], 16;\n"
                 :: "r"(dst), "l"(src));
}

// ---------------------------------------------------------------------------
// Fused fp32 -> fp16 weight convert (all 6 matrices, one launch).
// blockIdx.y selects matrix; small matrices early-exit excess blocks.
// ---------------------------------------------------------------------------
__global__ void convert_kernel(const float* __restrict__ s0, const float* __restrict__ s1,
                               const float* __restrict__ s2, const float* __restrict__ s3,
                               const float* __restrict__ s4, const float* __restrict__ s5,
                               __half* __restrict__ d0, __half* __restrict__ d1,
                               __half* __restrict__ d2, __half* __restrict__ d3,
                               __half* __restrict__ d4, __half* __restrict__ d5) {
    const int m = blockIdx.y;
    const float* s = (m == 0) ? s0 : (m == 1) ? s1 : (m == 2) ? s2
                   : (m == 3) ? s3 : (m == 4) ? s4 : s5;
    __half* d      = (m == 0) ? d0 : (m == 1) ? d1 : (m == 2) ? d2
                   : (m == 3) ? d3 : (m == 4) ? d4 : d5;
    const int n = (m < 4) ? Cdim * Cdim : Cdim * FF;
    const int idx = (blockIdx.x * 256 + threadIdx.x) * 8;
    if (idx >= n) return;
    const float4 a = *reinterpret_cast<const float4*>(s + idx);
    const float4 b = *reinterpret_cast<const float4*>(s + idx + 4);
    __half2 o[4];
    o[0] = __floats2half2_rn(a.x, a.y);
    o[1] = __floats2half2_rn(a.z, a.w);
    o[2] = __floats2half2_rn(b.x, b.y);
    o[3] = __floats2half2_rn(b.z, b.w);
    *reinterpret_cast<uint2*>(d + idx)     = *reinterpret_cast<const uint2*>(&o[0]);
    *reinterpret_cast<uint2*>(d + idx + 4) = *reinterpret_cast<const uint2*>(&o[2]);
}

// ---------------------------------------------------------------------------
// LayerNorm: one block per row (C=1024); fp16 output (feeds GEMM A).
// ---------------------------------------------------------------------------
__global__ void ln_kernel(const float4* __restrict__ x,
                          const float4* __restrict__ g,
                          const float4* __restrict__ b,
                          __half2* __restrict__ out) {
    const int row = blockIdx.x;
    const int t   = threadIdx.x;
    const float4 v = x[(size_t)row * 256 + t];
    float s = v.x + v.y + v.z + v.w;
    float q = v.x * v.x + v.y * v.y + v.z * v.z + v.w * v.w;
    #pragma unroll
    for (int o = 16; o > 0; o >>= 1) {
        s += __shfl_down_sync(0xffffffffu, s, o);
        q += __shfl_down_sync(0xffffffffu, q, o);
    }
    __shared__ float rs[8], rq[8];
    __shared__ float s_mean, s_rstd;
    const int wid = t >> 5, lane = t & 31;
    if (lane == 0) { rs[wid] = s; rq[wid] = q; }
    __syncthreads();
    if (t == 0) {
        float S = 0.f, Q = 0.f;
        #pragma unroll
        for (int i = 0; i < 8; i++) { S += rs[i]; Q += rq[i]; }
        const float mean = S * (1.0f / Cdim);
        const float var  = Q * (1.0f / Cdim) - mean * mean;
        s_mean = mean;
        s_rstd = rsqrtf(var + 1e-5f);
    }
    __syncthreads();
    const float mean = s_mean, rstd = s_rstd;
    const float4 G = g[t], Bv = b[t];
    out[(size_t)row * 512 + t * 2] =
        __floats2half2_rn((v.x - mean) * rstd * G.x + Bv.x,
                          (v.y - mean) * rstd * G.y + Bv.y);
    out[(size_t)row * 512 + t * 2 + 1] =
        __floats2half2_rn((v.z - mean) * rstd * G.z + Bv.z,
                          (v.w - mean) * rstd * G.w + Bv.w);
}

// ---------------------------------------------------------------------------
// fp16 tensor-core GEMM: C[M,N] = A[M,K] @ W[K,N] + bias (+ epilogue).
// 128x128x64 CTA tile, 8 warps (64x32 warp tile), m16n8k16 fp16 mma,
// cp.async 3-stage pipeline. A smem [m][k] 144B rows (direct ldsm),
// B smem [k][n] 272B rows (trans ldsm — same pattern as attention V).
// blockIdx.z selects (W, bias, out) — QKV fusion.
// ---------------------------------------------------------------------------
constexpr int EPI_BIAS = 0;
constexpr int EPI_GELU = 1;
constexpr int EPI_RES  = 2;

constexpr int HG_BK      = 64;
constexpr int HG_STAGES  = 3;
constexpr int HG_APADB   = 144;                       // A row: 128B data + 16B
constexpr int HG_BPADB   = 272;                       // B row: 256B data + 16B
constexpr int HG_ATILE_B = 128 * HG_APADB;            // 18432 B
constexpr int HG_BTILE_B = HG_BK * HG_BPADB;          // 17408 B
constexpr int HG_STAGE_B = HG_ATILE_B + HG_BTILE_B;   // 35840 B
constexpr int HG_SMEM    = HG_STAGES * HG_STAGE_B;    // 107520 B

template <int EPI, bool HOUT>
__global__ __launch_bounds__(256, 2)
void hgemm_kernel(const __half* __restrict__ A,
                  const __half* __restrict__ W0, const __half* __restrict__ W1p,
                  const __half* __restrict__ W2p,
                  const float* __restrict__ bias0, const float* __restrict__ bias1,
                  const float* __restrict__ bias2,
                  const float* __restrict__ res,
                  void* __restrict__ C0, void* __restrict__ C1,
                  void* __restrict__ C2,
                  int M, int N, int K) {
    const int z = blockIdx.z;
    const __half* W   = (z == 0) ? W0    : (z == 1) ? W1p   : W2p;
    const float* bias = (z == 0) ? bias0 : (z == 1) ? bias1 : bias2;
    void*        Cout = (z == 0) ? C0    : (z == 1) ? C1    : C2;

    extern __shared__ char smem[];
    const uint32_t sbase = (uint32_t)__cvta_generic_to_shared(smem);

    const int tid  = threadIdx.x;
    const int lane = tid & 31;
    const int warp = tid >> 5;
    const int wRow = (warp & 1) * 64;
    const int wCol = (warp >> 1) * 32;
    const int g    = lane >> 2;
    const int tk   = lane & 3;

    // ldmatrix per-lane selectors.
    const int aSelRow = (lane & 7) + ((lane >> 3) & 1) * 8;   // m within tile
    const int aSelK   = (lane >> 4) * 8;                      // k half
    const int bSelK   = (lane & 7) + ((lane >> 3) & 1) * 8;   // k row (trans)
    const int bSelN   = (lane >> 4) * 8;                      // n half

    const int cRow = blockIdx.y * 128;
    const int cCol = blockIdx.x * 128;
    const __half* Ag = A + (size_t)cRow * K;
    const __half* Wg = W + cCol;

    auto issue = [&](int k0, int stg) {
        const uint32_t aB = sbase + (uint32_t)stg * HG_STAGE_B;
        const uint32_t bB = aB + HG_ATILE_B;
        #pragma unroll
        for (int i = 0; i < 4; i++) {                 // A: 128 rows x 8 chunks
            const int id = tid + i * 256;
            const int r = id >> 3, c = id & 7;
            cp16(aB + (uint32_t)(r * HG_APADB + c * 16),
                 Ag + (size_t)r * K + k0 + c * 8);
        }
        #pragma unroll
        for (int i = 0; i < 4; i++) {                 // B: 64 k-rows x 16 chunks
            const int id = tid + i * 256;
            const int k = id >> 4, c = id & 15;
            cp16(bB + (uint32_t)(k * HG_BPADB + c * 16),
                 Wg + (size_t)(k0 + k) * N + c * 8);
        }
    };

    const int nIter = K / HG_BK;

    issue(0, 0);
    asm volatile("cp.async.commit_group;\n");
    issue(HG_BK, 1);
    asm volatile("cp.async.commit_group;\n");

    float acc[4][4][4] = {};

    for (int it = 0; it < nIter; it++) {
        asm volatile("cp.async.wait_group 1;\n");
        __syncthreads();

        if (it + 2 < nIter) issue((it + 2) * HG_BK, (it + 2) % HG_STAGES);
        asm volatile("cp.async.commit_group;\n");

        const uint32_t aB = sbase + (uint32_t)(it % HG_STAGES) * HG_STAGE_B;
        const uint32_t bB = aB + HG_ATILE_B;

        #pragma unroll
        for (int kc = 0; kc < 4; kc++) {              // four k16 chunks
            uint32_t afr[4][4], bfr[2][4];
            #pragma unroll
            for (int i = 0; i < 4; i++)
                ldsm4(afr[i], aB + (uint32_t)((wRow + i * 16 + aSelRow) * HG_APADB
                                              + (kc * 16 + aSelK) * 2));
            #pragma unroll
            for (int jp = 0; jp < 2; jp++)
                ldsm4t(bfr[jp], bB + (uint32_t)((kc * 16 + bSelK) * HG_BPADB
                                                + (wCol + jp * 16 + bSelN) * 2));
            #pragma unroll
            for (int i = 0; i < 4; i++)
                #pragma unroll
                for (int j = 0; j < 4; j++)
                    mma_f16(acc[i][j], afr[i],
                            bfr[j >> 1][(j & 1) * 2], bfr[j >> 1][(j & 1) * 2 + 1]);
        }
    }

    // Epilogue: c0,c1 at (row g, cols 2tk,2tk+1); c2,c3 at row g+8.
    #pragma unroll
    for (int i = 0; i < 4; i++) {
        const size_t rr0 = (size_t)cRow + wRow + i * 16 + g;
        const size_t rr1 = rr0 + 8;
        #pragma unroll
        for (int j = 0; j < 4; j++) {
            const int c = cCol + wCol + j * 8 + 2 * tk;
            const float b0 = bias[c], b1 = bias[c + 1];
            float v00 = acc[i][j][0] + b0, v01 = acc[i][j][1] + b1;
            float v10 = acc[i][j][2] + b0, v11 = acc[i][j][3] + b1;
            if (EPI == EPI_GELU) {
                v00 = 0.5f * v00 * (1.0f + erff(v00 * 0.70710678118654752f));
                v01 = 0.5f * v01 * (1.0f + erff(v01 * 0.70710678118654752f));
                v10 = 0.5f * v10 * (1.0f + erff(v10 * 0.70710678118654752f));
                v11 = 0.5f * v11 * (1.0f + erff(v11 * 0.70710678118654752f));
            }
            if (EPI == EPI_RES) {
                const float2 q0 = *reinterpret_cast<const float2*>(&res[rr0 * N + c]);
                const float2 q1 = *reinterpret_cast<const float2*>(&res[rr1 * N + c]);
                v00 += q0.x; v01 += q0.y;
                v10 += q1.x; v11 += q1.y;
            }
            if (HOUT) {
                __half* Ch = reinterpret_cast<__half*>(Cout);
                *reinterpret_cast<__half2*>(&Ch[rr0 * N + c]) = __floats2half2_rn(v00, v01);
                *reinterpret_cast<__half2*>(&Ch[rr1 * N + c]) = __floats2half2_rn(v10, v11);
            } else {
                float* Cf = reinterpret_cast<float*>(Cout);
                *reinterpret_cast<float2*>(&Cf[rr0 * N + c]) = make_float2(v00, v01);
                *reinterpret_cast<float2*>(&Cf[rr1 * N + c]) = make_float2(v10, v11);
            }
        }
    }
}

// ---------------------------------------------------------------------------
// Fused causal attention on mma.sync fp16, hd=64, ldmatrix fragments
// (unchanged from round 16 — proven).
// ---------------------------------------------------------------------------
constexpr int KPB = 144;   // bytes per smem row: 128 data + 16 pad

__global__ __launch_bounds__(256, 2)
void attn_h_kernel(const __half* __restrict__ Q, const __half* __restrict__ K,
                   const __half* __restrict__ V, __half* __restrict__ Y) {
    __shared__ __align__(16) unsigned char KsRaw[64 * KPB];
    __shared__ __align__(16) unsigned char VsRaw[64 * KPB];
    const uint32_t Kbase = (uint32_t)__cvta_generic_to_shared(KsRaw);
    const uint32_t Vbase = (uint32_t)__cvta_generic_to_shared(VsRaw);

    const int tid  = threadIdx.x;
    const int lane = tid & 31;
    const int warp = tid >> 5;
    const int g  = lane >> 2;
    const int tk = lane & 3;
    const int qTile = blockIdx.x;
    const int bh = blockIdx.y;
    const int b = bh >> 4, h = bh & 15;
    const size_t base = (size_t)b * Tdim * Cdim + (size_t)h * HD;
    const int q0 = qTile * 128 + warp * 16;

    const int kSelRow = (lane & 7) + (lane >> 4) * 8;
    const int kSelHd  = ((lane >> 3) & 1) * 8;
    const int vSelKey = (lane & 7) + ((lane >> 3) & 1) * 8;
    const int vSelHd  = (lane >> 4) * 8;

    uint32_t qf[4][4];
    #pragma unroll
    for (int c = 0; c < 4; c++) {
        const __half* q_r0 = Q + base + (size_t)(q0 + g)     * Cdim + c * 16;
        const __half* q_r1 = Q + base + (size_t)(q0 + g + 8) * Cdim + c * 16;
        qf[c][0] = *reinterpret_cast<const uint32_t*>(q_r0 + 2 * tk);
        qf[c][1] = *reinterpret_cast<const uint32_t*>(q_r1 + 2 * tk);
        qf[c][2] = *reinterpret_cast<const uint32_t*>(q_r0 + 2 * tk + 8);
        qf[c][3] = *reinterpret_cast<const uint32_t*>(q_r1 + 2 * tk + 8);
    }

    float oacc[8][4] = {};
    float lsum0 = 0.f, lsum1 = 0.f;

    const int nTiles = qTile * 2 + 2;
    for (int kt = 0; kt < nTiles; kt++) {
        const int kbase = kt * 64;
        #pragma unroll
        for (int r = 0; r < 2; r++) {
            const int lin = tid + r * 256;
            const int j = lin >> 3, c8 = lin & 7;
            const size_t go = base + (size_t)(kbase + j) * Cdim + c8 * 8;
            *reinterpret_cast<uint4*>(KsRaw + j * KPB + c8 * 16) =
                *reinterpret_cast<const uint4*>(K + go);
            *reinterpret_cast<uint4*>(VsRaw + j * KPB + c8 * 16) =
                *reinterpret_cast<const uint4*>(V + go);
        }
        __syncthreads();

        if (kbase <= q0 + 15) {
            const bool full = (kbase + 63 <= q0);
            #pragma unroll
            for (int kc = 0; kc < 4; kc++) {
                float s0a[4] = {0.f, 0.f, 0.f, 0.f};
                float s1a[4] = {0.f, 0.f, 0.f, 0.f};
                #pragma unroll
                for (int cd = 0; cd < 4; cd++) {
                    uint32_t kf[4];
                    ldsm4(kf, Kbase + (uint32_t)((kc * 16 + kSelRow) * KPB
                                                 + (cd * 16 + kSelHd) * 2));
                    mma_f16(s0a, qf[cd], kf[0], kf[1]);
                    mma_f16(s1a, qf[cd], kf[2], kf[3]);
                }
                float p00 = __expf(s0a[0] * 0.125f);
                float p01 = __expf(s0a[1] * 0.125f);
                float p02 = __expf(s0a[2] * 0.125f);
                float p03 = __expf(s0a[3] * 0.125f);
                float p10 = __expf(s1a[0] * 0.125f);
                float p11 = __expf(s1a[1] * 0.125f);
                float p12 = __expf(s1a[2] * 0.125f);
                float p13 = __expf(s1a[3] * 0.125f);
                if (!full) {
                    const int k0a = kbase + kc * 16 + 2 * tk;
                    const int k0b = k0a + 8;
                    const int rq0 = q0 + g, rq1 = q0 + g + 8;
                    if (k0a     > rq0) p00 = 0.f;
                    if (k0a + 1 > rq0) p01 = 0.f;
                    if (k0a     > rq1) p02 = 0.f;
                    if (k0a + 1 > rq1) p03 = 0.f;
                    if (k0b     > rq0) p10 = 0.f;
                    if (k0b + 1 > rq0) p11 = 0.f;
                    if (k0b     > rq1) p12 = 0.f;
                    if (k0b + 1 > rq1) p13 = 0.f;
                }
                lsum0 += p00 + p01 + p10 + p11;
                lsum1 += p02 + p03 + p12 + p13;
                uint32_t afr[4];
                afr[0] = pack_h2(p00, p01);
                afr[1] = pack_h2(p02, p03);
                afr[2] = pack_h2(p10, p11);
                afr[3] = pack_h2(p12, p13);
                #pragma unroll
                for (int nbp = 0; nbp < 4; nbp++) {
                    uint32_t vf[4];
                    ldsm4t(vf, Vbase + (uint32_t)((kc * 16 + vSelKey) * KPB
                                                  + (nbp * 16 + vSelHd) * 2));
                    mma_f16(oacc[2 * nbp],     afr, vf[0], vf[1]);
                    mma_f16(oacc[2 * nbp + 1], afr, vf[2], vf[3]);
                }
            }
        }
        __syncthreads();
    }

    lsum0 += __shfl_xor_sync(0xffffffffu, lsum0, 1);
    lsum0 += __shfl_xor_sync(0xffffffffu, lsum0, 2);
    lsum1 += __shfl_xor_sync(0xffffffffu, lsum1, 1);
    lsum1 += __shfl_xor_sync(0xffffffffu, lsum1, 2);
    const float inv0 = 1.0f / lsum0;
    const float inv1 = 1.0f / lsum1;

    #pragma unroll
    for (int nb = 0; nb < 8; nb++) {
        const int c = nb * 8 + 2 * tk;
        *reinterpret_cast<__half2*>(&Y[base + (size_t)(q0 + g) * Cdim + c]) =
            __floats2half2_rn(oacc[nb][0] * inv0, oacc[nb][1] * inv0);
        *reinterpret_cast<__half2*>(&Y[base + (size_t)(q0 + g + 8) * Cdim + c]) =
            __floats2half2_rn(oacc[nb][2] * inv1, oacc[nb][3] * inv1);
    }
}

// ---------------------------------------------------------------------------
// Launch sequence (graph-capturable).
// ---------------------------------------------------------------------------
extern "C" void kernel_launch(void* const* d_in, const int* in_sizes, int n_in,
                              void* d_out, int out_size) {
    (void)in_sizes; (void)n_in; (void)out_size;
    const float* x    = (const float*)d_in[0];
    const float* ln1g = (const float*)d_in[1];
    const float* ln1b = (const float*)d_in[2];
    const float* Wq   = (const float*)d_in[3];
    const float* bq   = (const float*)d_in[4];
    const float* Wk   = (const float*)d_in[5];
    const float* bk   = (const float*)d_in[6];
    const float* Wv   = (const float*)d_in[7];
    const float* bv   = (const float*)d_in[8];
    const float* Wp   = (const float*)d_in[9];
    const float* bp   = (const float*)d_in[10];
    const float* ln2g = (const float*)d_in[11];
    const float* ln2b = (const float*)d_in[12];
    const float* W1   = (const float*)d_in[13];
    const float* b1   = (const float*)d_in[14];
    const float* W2   = (const float*)d_in[15];
    const float* b2   = (const float*)d_in[16];
    float* out = (float*)d_out;

    __half *h, *qb, *kb, *vb, *y, *h2, *mb;
    __half *wq, *wk, *wv, *wp, *w1, *w2;
    float *x2;
    cudaGetSymbolAddress((void**)&h,  g_h);
    cudaGetSymbolAddress((void**)&qb, g_qb);
    cudaGetSymbolAddress((void**)&kb, g_kb);
    cudaGetSymbolAddress((void**)&vb, g_vb);
    cudaGetSymbolAddress((void**)&y,  g_y);
    cudaGetSymbolAddress((void**)&x2, g_x2);
    cudaGetSymbolAddress((void**)&h2, g_h2);
    cudaGetSymbolAddress((void**)&mb, g_mb);
    cudaGetSymbolAddress((void**)&wq, g_wq);
    cudaGetSymbolAddress((void**)&wk, g_wk);
    cudaGetSymbolAddress((void**)&wv, g_wv);
    cudaGetSymbolAddress((void**)&wp, g_wp);
    cudaGetSymbolAddress((void**)&w1, g_w1);
    cudaGetSymbolAddress((void**)&w2, g_w2);

    static bool attr_done = false;
    if (!attr_done) {
        cudaFuncSetAttribute((const void*)hgemm_kernel<EPI_BIAS, true>,
            cudaFuncAttributeMaxDynamicSharedMemorySize, HG_SMEM);
        cudaFuncSetAttribute((const void*)hgemm_kernel<EPI_GELU, true>,
            cudaFuncAttributeMaxDynamicSharedMemorySize, HG_SMEM);
        cudaFuncSetAttribute((const void*)hgemm_kernel<EPI_RES, false>,
            cudaFuncAttributeMaxDynamicSharedMemorySize, HG_SMEM);
        attr_done = true;
    }

    // One fused fp32->fp16 weight convert (native [K,N] layout preserved).
    convert_kernel<<<dim3(Cdim * FF / 2048, 6), 256>>>(
        Wq, Wk, Wv, Wp, W1, W2, wq, wk, wv, wp, w1, w2);

    const dim3 blk(256);
    const dim3 gQKV(Cdim / 128, MR / 128, 3);
    const dim3 gCC (Cdim / 128, MR / 128, 1);
    const dim3 gCF (FF   / 128, MR / 128, 1);
    const int  sm = HG_SMEM;

    ln_kernel<<<MR, 256>>>((const float4*)x, (const float4*)ln1g,
                           (const float4*)ln1b, (__half2*)h);
    hgemm_kernel<EPI_BIAS, true><<<gQKV, blk, sm>>>(
        h, wq, wk, wv, bq, bk, bv, nullptr, qb, kb, vb, MR, Cdim, Cdim);
    attn_h_kernel<<<dim3(Tdim / 128, Bdim * NH), 256>>>(qb, kb, vb, y);
    hgemm_kernel<EPI_RES, false><<<gCC, blk, sm>>>(
        y, wp, wp, wp, bp, bp, bp, x, x2, x2, x2, MR, Cdim, Cdim);
    ln_kernel<<<MR, 256>>>((const float4*)x2, (const float4*)ln2g,
                           (const float4*)ln2b, (__half2*)h2);
    hgemm_kernel<EPI_GELU, true><<<gCF, blk, sm>>>(
        h2, w1, w1, w1, b1, b1, b1, nullptr, mb, mb, mb, MR, FF, Cdim);
    hgemm_kernel<EPI_RES, false><<<gCC, blk, sm>>>(
        mb, w2, w2, w2, b2, b2, b2, x2, out, out, out, MR, Cdim, FF);
}